// round 1
// baseline (speedup 1.0000x reference)
#include <cuda_runtime.h>

// Problem constants (from reference: B, N, D, L = 32, 1000, 256, 3)
#define BB 32
#define NN 1000
#define DD 256
#define LL 3
#define CHUNKS 25
#define ROWS_PER_CHUNK 40   // 25 * 40 = 1000

// Scratch (no device allocation allowed -> __device__ globals)
__device__ float g_partial[BB * CHUNKS * DD];
__device__ float g_v[BB * DD];

// K1: partial sums of node_feature over the node axis.
// grid (B, CHUNKS), block D. Thread d sums 40 rows at stride D (coalesced across d).
__global__ void k_partial_mean(const float* __restrict__ nf) {
    const int b = blockIdx.x;
    const int c = blockIdx.y;
    const int d = threadIdx.x;
    const float* p = nf + (size_t)b * NN * DD + (size_t)c * ROWS_PER_CHUNK * DD + d;
    float s = 0.f;
#pragma unroll 8
    for (int r = 0; r < ROWS_PER_CHUNK; r++) {
        s += p[(size_t)r * DD];
    }
    g_partial[(b * CHUNKS + c) * DD + d] = s;
}

// K2: finish the mean, then 3 fused 256x256 GEMVs (+bias, ReLU between layers).
// One CTA per batch element; shared-memory vector; W reads are L2-resident
// (768 KB shared by all 32 CTAs).
__global__ void k_gcn_head(const float* __restrict__ Ws, const float* __restrict__ bs) {
    const int b = blockIdx.x;
    const int t = threadIdx.x;
    __shared__ float sv[DD];

    float s = 0.f;
#pragma unroll
    for (int c = 0; c < CHUNKS; c++) {
        s += g_partial[(b * CHUNKS + c) * DD + t];
    }
    sv[t] = s * (1.0f / (float)NN);
    __syncthreads();

#pragma unroll
    for (int l = 0; l < LL; l++) {
        const float* __restrict__ W = Ws + l * DD * DD;
        float acc = bs[l * DD + t];
#pragma unroll 8
        for (int d = 0; d < DD; d++) {
            acc = fmaf(sv[d], W[d * DD + t], acc);   // thread t reads col t: coalesced
        }
        __syncthreads();                 // everyone done reading sv before overwrite
        sv[t] = (l < LL - 1) ? fmaxf(acc, 0.f) : acc;
        __syncthreads();
    }
    g_v[b * DD + t] = sv[t];
}

// K3: out[0:B*N*D]        = node_feature + v[b,:] (broadcast over n)
//     out[B*N*D:2*B*N*D]  = node_feature (copy)
// float4 vectorized; D=256 divisible by 4 so a float4 never crosses the d boundary.
__global__ void k_out(const float* __restrict__ nf, float* __restrict__ out) {
    const int idx = blockIdx.x * blockDim.x + threadIdx.x;  // float4 index
    const int total4 = BB * NN * DD / 4;
    if (idx >= total4) return;

    const float4 a = reinterpret_cast<const float4*>(nf)[idx];

    const int i = idx << 2;
    const int b = i / (NN * DD);
    const int d = i & (DD - 1);
    const float4 v = *reinterpret_cast<const float4*>(g_v + b * DD + d);

    float4 r;
    r.x = a.x + v.x;
    r.y = a.y + v.y;
    r.z = a.z + v.z;
    r.w = a.w + v.w;

    float4* o4 = reinterpret_cast<float4*>(out);
    o4[idx] = r;            // update_node_feature
    o4[total4 + idx] = a;   // node_feature (tuple second element)
}

extern "C" void kernel_launch(void* const* d_in, const int* in_sizes, int n_in,
                              void* d_out, int out_size) {
    // Inputs per setup_inputs order: x (unused), node_feature, Ws, bs
    const float* nf = (const float*)d_in[1];
    const float* Ws = (const float*)d_in[2];
    const float* bs = (const float*)d_in[3];
    float* out = (float*)d_out;

    dim3 g1(BB, CHUNKS);
    k_partial_mean<<<g1, DD>>>(nf);
    k_gcn_head<<<BB, DD>>>(Ws, bs);

    const int total4 = BB * NN * DD / 4;            // 2,048,000
    const int threads = 256;
    const int blocks = (total4 + threads - 1) / threads;  // 8000
    k_out<<<blocks, threads>>>(nf, out);
}

// round 2
// speedup vs baseline: 2.7237x; 2.7237x over previous
#include <cuda_runtime.h>

// B, N, D, L = 32, 1000, 256, 3
#define BB 32
#define NN 1000
#define DD 256
#define LL 3
#define CHUNKS 10
#define ROWS_PER_CHUNK 100   // 10 * 100 = 1000

// Scratch (no device allocation allowed -> __device__ globals)
__device__ float g_partial[BB * CHUNKS * DD];
__device__ float g_v[BB * DD];

// ---------------------------------------------------------------------------
// K1: partial sums of node_feature over the node axis, float4-vectorized.
// grid (B, CHUNKS), block (64, 4). Thread (x,y): float4-column x, row-group y.
// Each thread issues 25 independent LDG.128 (high MLP), smem-reduce over y.
// ---------------------------------------------------------------------------
__global__ void k_partial_mean(const float* __restrict__ nf) {
    const int b = blockIdx.x;
    const int c = blockIdx.y;
    const int x = threadIdx.x;   // 0..63  (float4 column)
    const int y = threadIdx.y;   // 0..3   (row group)

    const float4* p = reinterpret_cast<const float4*>(
        nf + ((size_t)b * NN + (size_t)c * ROWS_PER_CHUNK) * DD);

    float4 s = make_float4(0.f, 0.f, 0.f, 0.f);
#pragma unroll
    for (int i = 0; i < 25; i++) {
        const int r = y + 4 * i;          // rows 0..99 covered by 4 groups
        const float4 a = p[r * 64 + x];   // 512B contiguous per warp
        s.x += a.x; s.y += a.y; s.z += a.z; s.w += a.w;
    }

    __shared__ float4 sm[4][64];
    sm[y][x] = s;
    __syncthreads();
    if (y == 0) {
        float4 t = sm[0][x];
        const float4 t1 = sm[1][x], t2 = sm[2][x], t3 = sm[3][x];
        t.x += t1.x + t2.x + t3.x;
        t.y += t1.y + t2.y + t3.y;
        t.z += t1.z + t2.z + t3.z;
        t.w += t1.w + t2.w + t3.w;
        reinterpret_cast<float4*>(g_partial)[(b * CHUNKS + c) * 64 + x] = t;
    }
}

// ---------------------------------------------------------------------------
// K2: finish the mean, then 3 fused 256x256 GEMVs (+bias, ReLU between).
// One CTA per batch, 1024 threads: out-column o = t&255, K-group g = t>>8.
// Each thread does only 64 FMAs/layer; 32 warps hide L2 latency.
// ---------------------------------------------------------------------------
__global__ void k_gcn_head(const float* __restrict__ Ws, const float* __restrict__ bs) {
    const int b = blockIdx.x;
    const int t = threadIdx.x;
    const int o = t & (DD - 1);
    const int g = t >> 8;       // 0..3

    __shared__ float sv[DD];
    __shared__ float part[4][DD];

    // finish mean: chunks strided over the 4 groups
    float s = 0.f;
    for (int c = g; c < CHUNKS; c += 4)
        s += g_partial[(b * CHUNKS + c) * DD + o];
    part[g][o] = s;
    __syncthreads();
    if (g == 0)
        sv[o] = (part[0][o] + part[1][o] + part[2][o] + part[3][o]) * (1.0f / (float)NN);
    __syncthreads();

#pragma unroll
    for (int l = 0; l < LL; l++) {
        const float* __restrict__ W = Ws + l * DD * DD;
        float acc = 0.f;
        const int k0 = g * 64;
#pragma unroll 8
        for (int k = k0; k < k0 + 64; k++)
            acc = fmaf(sv[k], W[k * DD + o], acc);   // coalesced col reads, L2-resident
        part[g][o] = acc;
        __syncthreads();                              // all sv reads done
        if (g == 0) {
            float r = part[0][o] + part[1][o] + part[2][o] + part[3][o] + bs[l * DD + o];
            sv[o] = (l < LL - 1) ? fmaxf(r, 0.f) : r;
        }
        __syncthreads();
    }
    if (g == 0) g_v[b * DD + o] = sv[o];
}

// ---------------------------------------------------------------------------
// K3: out[0 : BND]      = node_feature + v[b,:] (broadcast over n)
//     out[BND : 2*BND]  = node_feature (copy)
// 4 front-batched float4 loads per thread (MLP_p1=4), streaming stores (__stcs)
// so the 64MB output stream doesn't evict the L2-resident nf read.
// ---------------------------------------------------------------------------
__global__ void k_out(const float* __restrict__ nf, float* __restrict__ out) {
    const int total4 = BB * NN * DD / 4;                 // 2,048,000
    const int stride = gridDim.x * blockDim.x;           // 512,000
    const int i0 = blockIdx.x * blockDim.x + threadIdx.x;

    const float4* __restrict__ nf4 = reinterpret_cast<const float4*>(nf);
    float4* o4 = reinterpret_cast<float4*>(out);

    // indices: i0, i0+stride, i0+2s, i0+3s — exactly covers total4 (2000*256*4)
    const int ia = i0, ib = i0 + stride, ic = i0 + 2 * stride, id = i0 + 3 * stride;

    // front-batch the 4 loads
    const float4 a0 = nf4[ia];
    const float4 a1 = nf4[ib];
    const float4 a2 = nf4[ic];
    const float4 a3 = nf4[id];

#define DO_ONE(idx, a)                                                        \
    {                                                                         \
        const int i = (idx) << 2;                                             \
        const int bb = i / (NN * DD);                                         \
        const int dd = i & (DD - 1);                                          \
        const float4 v = *reinterpret_cast<const float4*>(g_v + bb * DD + dd);\
        float4 r;                                                             \
        r.x = (a).x + v.x; r.y = (a).y + v.y;                                 \
        r.z = (a).z + v.z; r.w = (a).w + v.w;                                 \
        __stcs(o4 + (idx), r);                                                \
        __stcs(o4 + total4 + (idx), (a));                                     \
    }

    DO_ONE(ia, a0)
    DO_ONE(ib, a1)
    DO_ONE(ic, a2)
    DO_ONE(id, a3)
#undef DO_ONE
}

extern "C" void kernel_launch(void* const* d_in, const int* in_sizes, int n_in,
                              void* d_out, int out_size) {
    // Inputs in metadata order: x (unused), node_feature, Ws, bs
    const float* nf = (const float*)d_in[1];
    const float* Ws = (const float*)d_in[2];
    const float* bs = (const float*)d_in[3];
    float* out = (float*)d_out;

    dim3 g1(BB, CHUNKS);
    dim3 b1(64, 4);
    k_partial_mean<<<g1, b1>>>(nf);

    k_gcn_head<<<BB, 1024>>>(Ws, bs);

    // 2000 blocks * 256 threads * 4 float4/thread = 2,048,000 = total4 exactly
    k_out<<<2000, 256>>>(nf, out);
}